// round 12
// baseline (speedup 1.0000x reference)
#include <cuda_runtime.h>
#include <cuda_fp16.h>
#include <math.h>
#include <stdint.h>

// ---------------- problem constants ----------------
#define B_DIM 4096
#define NH 512
#define NY 256
#define KSTATES 8

// ---------------- K1 tiling: 64x128, 4 warps (warp 64x32), 3 CTAs/SM ----------
#define K1_BM 64
#define K1_BN 128
#define K1_AST 8192                      // A stage bytes (64 rows x 128B)
#define K1_STAGE 24576                   // A 8KB + B 16KB
#define K1_NSTAGE 3
#define K1_SMEM (K1_NSTAGE * K1_STAGE)   // 72KB -> 3 CTAs/SM
#define K1_EPLDS 132

// ---------------- K2 tiling: 128x128, 3 stages, 2 CTAs/SM (R9) ----------------
#define BK 64
#define K2_STAGE 32768
#define K2_NSTAGE 3
#define K2_SMEM (K2_NSTAGE * K2_STAGE)   // 96KB

// ---------------- device scratch (allocation-free) ----------------
__device__ __align__(16) __half g_A16[(size_t)B_DIM * 1024];             // [x|h] fp16
__device__ __align__(16) __half g_B16[(size_t)NH * KSTATES * 1024];      // Bv interleaved rows (n*8+k)
__device__ __align__(16) __half g_Wo16[(size_t)NY * NH];                 // W_out fp16
__device__ __align__(16) __half g_h16[(size_t)KSTATES * B_DIM * NH];     // tanh(h_k) fp16, k-major

// ============================================================================
// One-shot fp32 -> fp16 conversion / packing of all GEMM operands
// ============================================================================
#define NA_G (B_DIM * 1024 / 4)
#define NB_G (NH * KSTATES * 1024 / 4)
#define NW_G (NY * NH / 4)

__global__ __launch_bounds__(256)
void cvt_all(const float* __restrict__ x, const float* __restrict__ h,
             const float* __restrict__ W_ih, const float* __restrict__ W_hh,
             const float* __restrict__ W_out,
             __half* __restrict__ A16, __half* __restrict__ B16,
             __half* __restrict__ Wo16)
{
    int idx = blockIdx.x * blockDim.x + threadIdx.x;
    const float* src;
    __half* dst;
    if (idx < NA_G) {
        int d = idx * 4, b = d >> 10, c = d & 1023;
        src = (c < 512) ? (x + (size_t)b * 512 + c) : (h + (size_t)b * 512 + (c - 512));
        dst = A16 + d;
    } else if (idx < NA_G + NB_G) {
        int d = (idx - NA_G) * 4;
        int row = d >> 10, c = d & 1023;
        int n = row >> 3, k = row & 7;                  // interleaved row = n*8+k
        src = (c < 512) ? (W_ih + (size_t)((k * 512) + n) * 512 + c)
                        : (W_hh + (size_t)((k * 512) + n) * 512 + (c - 512));
        dst = B16 + d;
    } else if (idx < NA_G + NB_G + NW_G) {
        int d = (idx - NA_G - NB_G) * 4;
        src = W_out + d;
        dst = Wo16 + d;
    } else {
        return;
    }
    float4 f = *(const float4*)src;
    __half2 lo = __floats2half2_rn(f.x, f.y);
    __half2 hi = __floats2half2_rn(f.z, f.w);
    *(uint2*)dst = make_uint2(*(uint32_t*)&lo, *(uint32_t*)&hi);
}

// ---------------- mma / ldmatrix helpers ----------------
static __device__ __forceinline__ void ldsm4(uint32_t& r0, uint32_t& r1,
                                             uint32_t& r2, uint32_t& r3, uint32_t addr) {
    asm volatile("ldmatrix.sync.aligned.m8n8.x4.shared.b16 {%0,%1,%2,%3}, [%4];"
                 : "=r"(r0), "=r"(r1), "=r"(r2), "=r"(r3) : "r"(addr));
}
static __device__ __forceinline__ void mma16816(float (&c)[4], const uint32_t (&a)[4],
                                                uint32_t b0, uint32_t b1) {
    asm volatile(
        "mma.sync.aligned.m16n8k16.row.col.f32.f16.f16.f32 "
        "{%0,%1,%2,%3}, {%4,%5,%6,%7}, {%8,%9}, {%0,%1,%2,%3};\n"
        : "+f"(c[0]), "+f"(c[1]), "+f"(c[2]), "+f"(c[3])
        : "r"(a[0]), "r"(a[1]), "r"(a[2]), "r"(a[3]), "r"(b0), "r"(b1));
}
// streaming stores (evict-first; outputs are never re-read)
static __device__ __forceinline__ void stcs_f2(float* p, float2 v) {
    asm volatile("st.global.cs.v2.f32 [%0], {%1,%2};" :: "l"(p), "f"(v.x), "f"(v.y) : "memory");
}
static __device__ __forceinline__ void stcs_f4(float* p, float4 v) {
    asm volatile("st.global.cs.v4.f32 [%0], {%1,%2,%3,%4};"
                 :: "l"(p), "f"(v.x), "f"(v.y), "f"(v.z), "f"(v.w) : "memory");
}
static __device__ __forceinline__ void stcs_f1(float* p, float v) {
    asm volatile("st.global.cs.f32 [%0], %1;" :: "l"(p), "f"(v) : "memory");
}

// ============================================================================
// K1: 64x128x1024 tile GEMM, 4 warps (warp tile 64x32), 3 CTAs/SM, 2048 CTAs.
// Per kk: 4 A-ldsm4 (warp-broadcast) + 2 B-ldsm4 -> 16 mma (ratio preserved).
// Output cols (n*8+k) interleaved == o_hk layout. Epilogue: tanh -> o_hk
// (streaming); pi-mix -> o_mix (streaming); smem restage -> h16 (k-major).
// ============================================================================
__global__ __launch_bounds__(128, 3)
void gemm_k1(const __half* __restrict__ A, const __half* __restrict__ Bv,
             const float* __restrict__ pi,
             float* __restrict__ o_hk, float* __restrict__ o_mix,
             __half* __restrict__ h16)
{
    extern __shared__ __align__(128) char smem[];
    uint32_t sbase;
    asm("{ .reg .u64 t; cvta.to.shared.u64 t, %1; cvt.u32.u64 %0, t; }"
        : "=r"(sbase) : "l"(smem));

    const int tid = threadIdx.x, wid = tid >> 5, lane = tid & 31;
    const int gid = lane >> 2, tg = lane & 3;
    const int bm = blockIdx.y * K1_BM, bn = blockIdx.x * K1_BN;

    float acc[4][4][4];
    #pragma unroll
    for (int im = 0; im < 4; ++im)
        #pragma unroll
        for (int in = 0; in < 4; ++in)
            #pragma unroll
            for (int q = 0; q < 4; ++q) acc[im][in][q] = 0.0f;

    // cp.async: A 2 thr/row x 4 chunks; B 1 thr/row x 8 chunks (128 threads)
    const int rowA_ld = tid >> 1, cbA = (tid & 1) * 4;
    const __half* gA = A + (size_t)(bm + rowA_ld) * 1024;
    const __half* gB = Bv + (size_t)(bn + tid) * 1024;

    auto issue = [&](int kt, int bi) {
        const uint32_t st = sbase + bi * K1_STAGE;
        const __half* ga = gA + kt * BK;
        const __half* gb = gB + kt * BK;
        #pragma unroll
        for (int i = 0; i < 4; ++i) {
            int c = cbA + i;
            uint32_t sw = (uint32_t)rowA_ld * 128 + (uint32_t)((c ^ (rowA_ld & 7)) * 16);
            asm volatile("cp.async.cg.shared.global [%0], [%1], 16;"
                         :: "r"(st + sw), "l"(ga + c * 8));
        }
        #pragma unroll
        for (int c = 0; c < 8; ++c) {
            uint32_t sw = (uint32_t)tid * 128 + (uint32_t)((c ^ (tid & 7)) * 16);
            asm volatile("cp.async.cg.shared.global [%0], [%1], 16;"
                         :: "r"(st + K1_AST + sw), "l"(gb + c * 8));
        }
    };

    const int rwi  = lane & 7;
    const int hi8  = (lane >> 3) & 1;
    const int hi16 = lane >> 4;
    const int rowA0 = hi8 * 8 + rwi;              // +im*16 (warp-broadcast A)
    const int rowB0 = wid * 32 + hi8 * 8 + rwi;   // +j*16

    constexpr int NSTEPS = 1024 / BK;   // 16

    #pragma unroll
    for (int s = 0; s < K1_NSTAGE - 1; ++s) {
        issue(s, s);
        asm volatile("cp.async.commit_group;" ::: "memory");
    }

    int bi = 0, bnx = K1_NSTAGE - 1;
    for (int it = 0; it < NSTEPS; ++it) {
        asm volatile("cp.async.wait_group %0;" :: "n"(K1_NSTAGE - 2) : "memory");
        __syncthreads();

        const int nx = it + K1_NSTAGE - 1;
        if (nx < NSTEPS) issue(nx, bnx);
        asm volatile("cp.async.commit_group;" ::: "memory");

        const uint32_t sA = sbase + bi * K1_STAGE;
        const uint32_t sB = sA + K1_AST;
        if (++bi == K1_NSTAGE) bi = 0;
        if (++bnx == K1_NSTAGE) bnx = 0;

        #pragma unroll
        for (int kk = 0; kk < 4; ++kk) {
            const uint32_t chx = (uint32_t)(((2 * kk + hi16) ^ rwi) << 4);
            uint32_t a[4][4];
            #pragma unroll
            for (int im = 0; im < 4; ++im)
                ldsm4(a[im][0], a[im][1], a[im][2], a[im][3],
                      sA + (uint32_t)(rowA0 + im * 16) * 128 + chx);
            #pragma unroll
            for (int j = 0; j < 2; ++j) {
                uint32_t q0, q1, q2, q3;
                ldsm4(q0, q1, q2, q3, sB + (uint32_t)(rowB0 + j * 16) * 128 + chx);
                #pragma unroll
                for (int im = 0; im < 4; ++im) {
                    mma16816(acc[im][2 * j],     a[im], q0, q2);
                    mma16816(acc[im][2 * j + 1], a[im], q1, q3);
                }
            }
        }
    }

    // ---------- epilogue ----------
    __syncthreads();
    __half* ep = (__half*)smem;          // 64 x K1_EPLDS staging
    const int n0 = bn >> 3;              // global n base (16 n's per CTA)

    #pragma unroll
    for (int im = 0; im < 4; ++im) {
        const int rA = bm + im * 16 + gid;
        const float2 pA = *(const float2*)(pi + (size_t)rA * 8 + tg * 2);
        const float2 pB = *(const float2*)(pi + (size_t)(rA + 8) * 8 + tg * 2);
        #pragma unroll
        for (int in = 0; in < 4; ++in) {
            const int c0 = bn + wid * 32 + in * 8 + tg * 2;
            float v0 = tanhf(acc[im][in][0]);
            float v1 = tanhf(acc[im][in][1]);
            float v2 = tanhf(acc[im][in][2]);
            float v3 = tanhf(acc[im][in][3]);

            stcs_f2(o_hk + (size_t)rA * 4096 + c0,       make_float2(v0, v1));
            stcs_f2(o_hk + (size_t)(rA + 8) * 4096 + c0, make_float2(v2, v3));

            float m0 = v0 * pA.x + v1 * pA.y;
            float m1 = v2 * pB.x + v3 * pB.y;
            m0 += __shfl_xor_sync(0xFFFFFFFFu, m0, 1);
            m0 += __shfl_xor_sync(0xFFFFFFFFu, m0, 2);
            m1 += __shfl_xor_sync(0xFFFFFFFFu, m1, 1);
            m1 += __shfl_xor_sync(0xFFFFFFFFu, m1, 2);
            if (tg == 0) {
                const int ng = n0 + wid * 4 + in;
                stcs_f1(o_mix + (size_t)rA * 512 + ng, m0);
                stcs_f1(o_mix + (size_t)(rA + 8) * 512 + ng, m1);
            }

            const int rl = im * 16 + gid;
            const int cl = wid * 32 + in * 8 + tg * 2;
            __half2 h01 = __floats2half2_rn(v0, v1);
            __half2 h23 = __floats2half2_rn(v2, v3);
            *(__half2*)(ep + (size_t)rl * K1_EPLDS + cl)       = h01;
            *(__half2*)(ep + (size_t)(rl + 8) * K1_EPLDS + cl) = h23;
        }
    }
    __syncthreads();

    // restage to h16 k-major: each warp owns 2 states (kst = wid, wid+4)
    {
        const int rr = lane >> 3;       // 0..3
        const int nn = lane & 7;        // n-pair index
        #pragma unroll
        for (int s = 0; s < 2; ++s) {
            const int kst = wid + s * 4;
            __half* plane = h16 + (size_t)kst * ((size_t)B_DIM * 512);
            #pragma unroll
            for (int i = 0; i < 16; ++i) {
                const int row = i * 4 + rr;
                __half h0 = ep[(size_t)row * K1_EPLDS + (2 * nn) * 8 + kst];
                __half h1 = ep[(size_t)row * K1_EPLDS + (2 * nn + 1) * 8 + kst];
                *(__half2*)(plane + (size_t)(bm + row) * 512 + n0 + 2 * nn) =
                    __halves2half2(h0, h1);
            }
        }
    }
}

// ============================================================================
// K2 mainloop (f32 accumulate, 128x128 tile) — unchanged from R9.
// ============================================================================
static __device__ __forceinline__
void mainloop_k2(const __half* __restrict__ gA, const __half* __restrict__ gB,
                 uint32_t sbase, float (&acc)[2][8][4])
{
    const int tid = threadIdx.x, wid = tid >> 5, lane = tid & 31;
    const int warpM = wid & 3, warpN = wid >> 2;

    const int row_ld = wid * 16 + (lane >> 1);
    const int cb = (lane & 1) * 4;

    auto issue = [&](int kt, int bi) {
        const uint32_t sA = sbase + bi * K2_STAGE;
        const __half* ga = gA + kt * BK;
        const __half* gb = gB + kt * BK;
        #pragma unroll
        for (int i = 0; i < 4; ++i) {
            int c = cb + i;
            uint32_t sw = (uint32_t)row_ld * 128 + (uint32_t)((c ^ (row_ld & 7)) * 16);
            asm volatile("cp.async.cg.shared.global [%0], [%1], 16;"
                         :: "r"(sA + sw), "l"(ga + c * 8));
            asm volatile("cp.async.cg.shared.global [%0], [%1], 16;"
                         :: "r"(sA + 16384 + sw), "l"(gb + c * 8));
        }
    };

    const int rwi  = lane & 7;
    const int hi8  = (lane >> 3) & 1;
    const int hi16 = lane >> 4;
    const int rowA0 = warpM * 32 + hi8 * 8 + rwi;
    const int rowB0 = warpN * 64 + hi8 * 8 + rwi;

    constexpr int NSTEPS = 512 / BK;    // 8

    #pragma unroll
    for (int s = 0; s < K2_NSTAGE - 1; ++s) {
        issue(s, s);
        asm volatile("cp.async.commit_group;" ::: "memory");
    }

    int bi = 0, bnx = K2_NSTAGE - 1;
    for (int it = 0; it < NSTEPS; ++it) {
        asm volatile("cp.async.wait_group %0;" :: "n"(K2_NSTAGE - 2) : "memory");
        __syncthreads();

        const int nx = it + K2_NSTAGE - 1;
        if (nx < NSTEPS) issue(nx, bnx);
        asm volatile("cp.async.commit_group;" ::: "memory");

        const uint32_t sA = sbase + bi * K2_STAGE;
        const uint32_t sB = sA + 16384;
        if (++bi == K2_NSTAGE) bi = 0;
        if (++bnx == K2_NSTAGE) bnx = 0;

        #pragma unroll
        for (int kk = 0; kk < 4; ++kk) {
            const uint32_t chx = (uint32_t)(((2 * kk + hi16) ^ rwi) << 4);
            uint32_t a[2][4];
            #pragma unroll
            for (int im = 0; im < 2; ++im)
                ldsm4(a[im][0], a[im][1], a[im][2], a[im][3],
                      sA + (uint32_t)(rowA0 + im * 16) * 128 + chx);
            #pragma unroll
            for (int j = 0; j < 4; ++j) {
                uint32_t q0, q1, q2, q3;
                ldsm4(q0, q1, q2, q3, sB + (uint32_t)(rowB0 + j * 16) * 128 + chx);
                #pragma unroll
                for (int im = 0; im < 2; ++im) {
                    mma16816(acc[im][2 * j],     a[im], q0, q2);
                    mma16816(acc[im][2 * j + 1], a[im], q1, q3);
                }
            }
        }
    }
}

// ============================================================================
// K2 (fused): CTA covers 16 batch rows x ALL 8 states x 128 y-cols. (R9)
// ============================================================================
__global__ __launch_bounds__(256, 2)
void gemm_k2(const __half* __restrict__ h16, const __half* __restrict__ Wo,
             const float* __restrict__ pi,
             float* __restrict__ o_outk, float* __restrict__ o_out)
{
    extern __shared__ __align__(128) char smem[];
    uint32_t sbase;
    asm("{ .reg .u64 t; cvta.to.shared.u64 t, %1; cvt.u32.u64 %0, t; }"
        : "=r"(sbase) : "l"(smem));

    const int tid = threadIdx.x, wid = tid >> 5, lane = tid & 31;
    const int gid = lane >> 2, tg = lane & 3;
    const int warpM = wid & 3, warpN = wid >> 2;
    const int bm = blockIdx.y;           // 16-row batch slab
    const int bn = blockIdx.x * 128;     // y base

    float acc[2][8][4];
    #pragma unroll
    for (int im = 0; im < 2; ++im)
        #pragma unroll
        for (int in = 0; in < 8; ++in)
            #pragma unroll
            for (int q = 0; q < 4; ++q) acc[im][in][q] = 0.0f;

    {
        const int row_ld = wid * 16 + (lane >> 1);
        const size_t plane = (size_t)B_DIM * 512;
        const __half* gA = h16 + (size_t)(row_ld & 7) * plane
                               + ((size_t)bm * 16 + (row_ld >> 3)) * 512;
        const __half* gB = Wo + (size_t)(bn + row_ld) * 512;
        mainloop_k2(gA, gB, sbase, acc);
    }

    // ---------- fused epilogue ----------
    __syncthreads();
    float* stage = (float*)smem;         // [16][1024] floats = 64KB

    #pragma unroll
    for (int im = 0; im < 2; ++im) {
        const int brow = warpM * 4 + im * 2;
        const int b0 = bm * 16 + brow;
        const float pk0 = pi[(size_t)b0 * 8 + gid];
        const float pk1 = pi[(size_t)(b0 + 1) * 8 + gid];
        #pragma unroll
        for (int in = 0; in < 8; ++in) {
            const int y = warpN * 64 + in * 8 + tg * 2;   // local y
            float v0 = acc[im][in][0], v1 = acc[im][in][1];
            float v2 = acc[im][in][2], v3 = acc[im][in][3];

            stage[brow * 1024 + y * 8 + gid]             = v0;
            stage[brow * 1024 + (y + 1) * 8 + gid]       = v1;
            stage[(brow + 1) * 1024 + y * 8 + gid]       = v2;
            stage[(brow + 1) * 1024 + (y + 1) * 8 + gid] = v3;

            float m0 = v0 * pk0, m1 = v1 * pk0;
            float m2 = v2 * pk1, m3 = v3 * pk1;
            #pragma unroll
            for (int d = 4; d < 32; d <<= 1) {
                m0 += __shfl_xor_sync(0xFFFFFFFFu, m0, d);
                m1 += __shfl_xor_sync(0xFFFFFFFFu, m1, d);
                m2 += __shfl_xor_sync(0xFFFFFFFFu, m2, d);
                m3 += __shfl_xor_sync(0xFFFFFFFFu, m3, d);
            }
            if (gid == 0) {
                stcs_f1(o_out + (size_t)b0 * 256 + bn + y, m0);
                stcs_f1(o_out + (size_t)b0 * 256 + bn + y + 1, m1);
                stcs_f1(o_out + (size_t)(b0 + 1) * 256 + bn + y, m2);
                stcs_f1(o_out + (size_t)(b0 + 1) * 256 + bn + y + 1, m3);
            }
        }
    }
    __syncthreads();

    #pragma unroll
    for (int i = 0; i < 16; ++i) {
        const int idx = i * 256 + tid;
        const int brow = idx >> 8;
        const int chunk = idx & 255;
        float4 v = *(float4*)&stage[brow * 1024 + chunk * 4];
        stcs_f4(o_outk + ((size_t)(bm * 16 + brow) * 256 + bn) * 8 + chunk * 4, v);
    }
}

extern "C" void kernel_launch(void* const* d_in, const int* in_sizes, int n_in,
                              void* d_out, int out_size)
{
    const float* x     = (const float*)d_in[0];
    const float* h     = (const float*)d_in[1];
    const float* pi    = (const float*)d_in[2];
    const float* W_ih  = (const float*)d_in[3];
    const float* W_hh  = (const float*)d_in[4];
    const float* W_out = (const float*)d_in[5];
    float* out = (float*)d_out;

    __half *A16, *B16, *Wo16, *h16;
    cudaGetSymbolAddress((void**)&A16, g_A16);
    cudaGetSymbolAddress((void**)&B16, g_B16);
    cudaGetSymbolAddress((void**)&Wo16, g_Wo16);
    cudaGetSymbolAddress((void**)&h16, g_h16);

    // output layout: tuple (out, h_mix, out_k, h_k) concatenated, each row-major
    float* o_out  = out;                                   // (B, NY)
    float* o_mix  = o_out  + (size_t)B_DIM * NY;           // (B, NH)
    float* o_outk = o_mix  + (size_t)B_DIM * NH;           // (B, NY, K)
    float* o_hk   = o_outk + (size_t)B_DIM * NY * KSTATES; // (B, NH, K)

    cudaFuncSetAttribute(gemm_k1, cudaFuncAttributeMaxDynamicSharedMemorySize, K1_SMEM);
    cudaFuncSetAttribute(gemm_k2, cudaFuncAttributeMaxDynamicSharedMemorySize, K2_SMEM);

    // K0: fp16 operand packing (A16=[x|h], B16=interleaved Bv, Wo16)
    cvt_all<<<(NA_G + NB_G + NW_G + 255) / 256, 256>>>(
        x, h, W_ih, W_hh, W_out, A16, B16, Wo16);

    // K1: big GEMM, 2048 small CTAs (warp ratio preserved) -> o_hk + o_mix + h16
    gemm_k1<<<dim3(4096 / K1_BN, B_DIM / K1_BM), 128, K1_SMEM>>>(
        A16, B16, pi, o_hk, o_mix, h16);

    // K2: fused out_k + out (interleave + pi-mix in epilogue)
    gemm_k2<<<dim3(NY / 128, B_DIM / 16), 256, K2_SMEM>>>(
        h16, Wo16, pi, o_outk, o_out);
}

// round 13
// speedup vs baseline: 1.3276x; 1.3276x over previous
#include <cuda_runtime.h>
#include <cuda_fp16.h>
#include <math.h>
#include <stdint.h>

// ---------------- problem constants ----------------
#define B_DIM 4096
#define NH 512
#define NY 256
#define KSTATES 8

// ---------------- GEMM tiling ----------------
#define BM 128
#define BN 128
#define BK 64              // halves per k-stage (128 bytes/row)
#define NSTAGE 3
#define STAGE_BYTES 32768  // A 16KB + B 16KB
#define SMEM_BYTES (NSTAGE * STAGE_BYTES)   // 96KB -> 2 CTAs/SM
#define EP_LDS 132         // K1 epilogue staging row stride (halves)

// ---------------- device scratch (allocation-free) ----------------
__device__ __align__(16) __half g_A16[(size_t)B_DIM * 1024];             // [x|h] fp16
__device__ __align__(16) __half g_B16[(size_t)NH * KSTATES * 1024];      // Bv interleaved rows (n*8+k)
__device__ __align__(16) __half g_Wo16[(size_t)NY * NH];                 // W_out fp16
__device__ __align__(16) __half g_h16[(size_t)KSTATES * B_DIM * NH];     // tanh(h_k) fp16, k-major

// ============================================================================
// One-shot fp32 -> fp16 conversion / packing of all GEMM operands
// ============================================================================
#define NA_G (B_DIM * 1024 / 4)
#define NB_G (NH * KSTATES * 1024 / 4)
#define NW_G (NY * NH / 4)

__global__ __launch_bounds__(256)
void cvt_all(const float* __restrict__ x, const float* __restrict__ h,
             const float* __restrict__ W_ih, const float* __restrict__ W_hh,
             const float* __restrict__ W_out,
             __half* __restrict__ A16, __half* __restrict__ B16,
             __half* __restrict__ Wo16)
{
    int idx = blockIdx.x * blockDim.x + threadIdx.x;
    const float* src;
    __half* dst;
    if (idx < NA_G) {
        int d = idx * 4, b = d >> 10, c = d & 1023;
        src = (c < 512) ? (x + (size_t)b * 512 + c) : (h + (size_t)b * 512 + (c - 512));
        dst = A16 + d;
    } else if (idx < NA_G + NB_G) {
        int d = (idx - NA_G) * 4;
        int row = d >> 10, c = d & 1023;
        int n = row >> 3, k = row & 7;                  // interleaved row = n*8+k
        src = (c < 512) ? (W_ih + (size_t)((k * 512) + n) * 512 + c)
                        : (W_hh + (size_t)((k * 512) + n) * 512 + (c - 512));
        dst = B16 + d;
    } else if (idx < NA_G + NB_G + NW_G) {
        int d = (idx - NA_G - NB_G) * 4;
        src = W_out + d;
        dst = Wo16 + d;
    } else {
        return;
    }
    float4 f = *(const float4*)src;
    __half2 lo = __floats2half2_rn(f.x, f.y);
    __half2 hi = __floats2half2_rn(f.z, f.w);
    *(uint2*)dst = make_uint2(*(uint32_t*)&lo, *(uint32_t*)&hi);
}

// ---------------- mma / ldmatrix helpers ----------------
static __device__ __forceinline__ void ldsm4(uint32_t& r0, uint32_t& r1,
                                             uint32_t& r2, uint32_t& r3, uint32_t addr) {
    asm volatile("ldmatrix.sync.aligned.m8n8.x4.shared.b16 {%0,%1,%2,%3}, [%4];"
                 : "=r"(r0), "=r"(r1), "=r"(r2), "=r"(r3) : "r"(addr));
}
static __device__ __forceinline__ void mma16816(float (&c)[4], const uint32_t (&a)[4],
                                                uint32_t b0, uint32_t b1) {
    asm volatile(
        "mma.sync.aligned.m16n8k16.row.col.f32.f16.f16.f32 "
        "{%0,%1,%2,%3}, {%4,%5,%6,%7}, {%8,%9}, {%0,%1,%2,%3};\n"
        : "+f"(c[0]), "+f"(c[1]), "+f"(c[2]), "+f"(c[3])
        : "r"(a[0]), "r"(a[1]), "r"(a[2]), "r"(a[3]), "r"(b0), "r"(b1));
}
// streaming stores (evict-first; outputs are never re-read)
static __device__ __forceinline__ void stcs_f2(float* p, float2 v) {
    asm volatile("st.global.cs.v2.f32 [%0], {%1,%2};" :: "l"(p), "f"(v.x), "f"(v.y) : "memory");
}
static __device__ __forceinline__ void stcs_f4(float* p, float4 v) {
    asm volatile("st.global.cs.v4.f32 [%0], {%1,%2,%3,%4};"
                 :: "l"(p), "f"(v.x), "f"(v.y), "f"(v.z), "f"(v.w) : "memory");
}
static __device__ __forceinline__ void stcs_f1(float* p, float v) {
    asm volatile("st.global.cs.f32 [%0], %1;" :: "l"(p), "f"(v) : "memory");
}

// ============================================================================
// Mainloop core: acc[2][8][4] += A_tile(128,KD) * B_tile(128,KD)^T
// fp16 operands, SW128-style XOR swizzle, cp.async 3-stage pipeline,
// ldmatrix fragments. 8 warps as 4(M) x 2(N), warp tile 32x64.
// gA/gB are this thread's cp.async row base pointers.
// ============================================================================
template<int KD>
static __device__ __forceinline__
void mainloop_ptr(const __half* __restrict__ gA, const __half* __restrict__ gB,
                  uint32_t sbase, float (&acc)[2][8][4])
{
    const int tid = threadIdx.x, wid = tid >> 5, lane = tid & 31;
    const int warpM = wid & 3, warpN = wid >> 2;

    const int row_ld = wid * 16 + (lane >> 1);
    const int cb = (lane & 1) * 4;

    auto issue = [&](int kt, int bi) {
        const uint32_t sA = sbase + bi * STAGE_BYTES;
        const __half* ga = gA + kt * BK;
        const __half* gb = gB + kt * BK;
        #pragma unroll
        for (int i = 0; i < 4; ++i) {
            int c = cb + i;
            uint32_t sw = (uint32_t)row_ld * 128 + (uint32_t)((c ^ (row_ld & 7)) * 16);
            asm volatile("cp.async.cg.shared.global [%0], [%1], 16;"
                         :: "r"(sA + sw), "l"(ga + c * 8));
            asm volatile("cp.async.cg.shared.global [%0], [%1], 16;"
                         :: "r"(sA + 16384 + sw), "l"(gb + c * 8));
        }
    };

    const int rwi  = lane & 7;
    const int hi8  = (lane >> 3) & 1;
    const int hi16 = lane >> 4;
    const int rowA0 = warpM * 32 + hi8 * 8 + rwi;
    const int rowB0 = warpN * 64 + hi8 * 8 + rwi;

    constexpr int NSTEPS = KD / BK;

    #pragma unroll
    for (int s = 0; s < NSTAGE - 1; ++s) {
        issue(s, s);
        asm volatile("cp.async.commit_group;" ::: "memory");
    }

    int bi = 0, bnx = NSTAGE - 1;
    for (int it = 0; it < NSTEPS; ++it) {
        asm volatile("cp.async.wait_group %0;" :: "n"(NSTAGE - 2) : "memory");
        __syncthreads();

        const int nx = it + NSTAGE - 1;
        if (nx < NSTEPS) issue(nx, bnx);
        asm volatile("cp.async.commit_group;" ::: "memory");

        const uint32_t sA = sbase + bi * STAGE_BYTES;
        const uint32_t sB = sA + 16384;
        if (++bi == NSTAGE) bi = 0;
        if (++bnx == NSTAGE) bnx = 0;

        #pragma unroll
        for (int kk = 0; kk < 4; ++kk) {
            const uint32_t chx = (uint32_t)(((2 * kk + hi16) ^ rwi) << 4);
            uint32_t a[2][4];
            #pragma unroll
            for (int im = 0; im < 2; ++im)
                ldsm4(a[im][0], a[im][1], a[im][2], a[im][3],
                      sA + (uint32_t)(rowA0 + im * 16) * 128 + chx);
            #pragma unroll
            for (int j = 0; j < 4; ++j) {
                uint32_t q0, q1, q2, q3;
                ldsm4(q0, q1, q2, q3, sB + (uint32_t)(rowB0 + j * 16) * 128 + chx);
                #pragma unroll
                for (int im = 0; im < 2; ++im) {
                    mma16816(acc[im][2 * j],     a[im], q0, q2);
                    mma16816(acc[im][2 * j + 1], a[im], q1, q3);
                }
            }
        }
    }
}

// ============================================================================
// K1: big GEMM (4096 x 4096 x 1024). Output cols are (n*8+k) interleaved ==
// o_hk layout. Epilogue: tanh -> o_hk f32 (streaming); quad-shuffle pi-mix ->
// o_mix (streaming); smem restage -> h16 (k-major fp16, K2's A input).
// ============================================================================
__global__ __launch_bounds__(256, 2)
void gemm_k1(const __half* __restrict__ A, const __half* __restrict__ Bv,
             const float* __restrict__ pi,
             float* __restrict__ o_hk, float* __restrict__ o_mix,
             __half* __restrict__ h16)
{
    extern __shared__ __align__(128) char smem[];
    uint32_t sbase;
    asm("{ .reg .u64 t; cvta.to.shared.u64 t, %1; cvt.u32.u64 %0, t; }"
        : "=r"(sbase) : "l"(smem));

    const int tid = threadIdx.x, wid = tid >> 5, lane = tid & 31;
    const int gid = lane >> 2, tg = lane & 3;
    const int warpM = wid & 3, warpN = wid >> 2;
    const int bm = blockIdx.y * BM, bn = blockIdx.x * BN;

    float acc[2][8][4];
    #pragma unroll
    for (int im = 0; im < 2; ++im)
        #pragma unroll
        for (int in = 0; in < 8; ++in)
            #pragma unroll
            for (int q = 0; q < 4; ++q) acc[im][in][q] = 0.0f;

    {
        const int row_ld = wid * 16 + (lane >> 1);
        const __half* gA = A + (size_t)(bm + row_ld) * 1024;
        const __half* gB = Bv + (size_t)(bn + row_ld) * 1024;
        mainloop_ptr<1024>(gA, gB, sbase, acc);
    }

    // ---------- epilogue ----------
    __syncthreads();
    __half* ep = (__half*)smem;          // 128 x EP_LDS staging
    const int n0 = bn >> 3;              // global n base for this CTA (16 n's)

    #pragma unroll
    for (int im = 0; im < 2; ++im) {
        const int rA = bm + warpM * 32 + im * 16 + gid;
        const float2 pA = *(const float2*)(pi + (size_t)rA * 8 + tg * 2);
        const float2 pB = *(const float2*)(pi + (size_t)(rA + 8) * 8 + tg * 2);
        #pragma unroll
        for (int in = 0; in < 8; ++in) {
            const int c0 = bn + warpN * 64 + in * 8 + tg * 2;
            float v0 = tanhf(acc[im][in][0]);
            float v1 = tanhf(acc[im][in][1]);
            float v2 = tanhf(acc[im][in][2]);
            float v3 = tanhf(acc[im][in][3]);

            stcs_f2(o_hk + (size_t)rA * 4096 + c0,       make_float2(v0, v1));
            stcs_f2(o_hk + (size_t)(rA + 8) * 4096 + c0, make_float2(v2, v3));

            float m0 = v0 * pA.x + v1 * pA.y;
            float m1 = v2 * pB.x + v3 * pB.y;
            m0 += __shfl_xor_sync(0xFFFFFFFFu, m0, 1);
            m0 += __shfl_xor_sync(0xFFFFFFFFu, m0, 2);
            m1 += __shfl_xor_sync(0xFFFFFFFFu, m1, 1);
            m1 += __shfl_xor_sync(0xFFFFFFFFu, m1, 2);
            if (tg == 0) {
                const int ng = n0 + warpN * 8 + in;
                stcs_f1(o_mix + (size_t)rA * 512 + ng, m0);
                stcs_f1(o_mix + (size_t)(rA + 8) * 512 + ng, m1);
            }

            const int rl = warpM * 32 + im * 16 + gid;
            const int cl = warpN * 64 + in * 8 + tg * 2;
            __half2 h01 = __floats2half2_rn(v0, v1);
            __half2 h23 = __floats2half2_rn(v2, v3);
            *(__half2*)(ep + (size_t)rl * EP_LDS + cl)       = h01;
            *(__half2*)(ep + (size_t)(rl + 8) * EP_LDS + cl) = h23;
        }
    }
    __syncthreads();

    // restage to h16 k-major: warp wid owns state k = wid
    {
        const int kst = wid;
        __half* plane = h16 + (size_t)kst * ((size_t)B_DIM * 512);
        const int rr = lane >> 3;
        const int nn = lane & 7;
        #pragma unroll
        for (int i = 0; i < 32; ++i) {
            const int row = i * 4 + rr;
            __half h0 = ep[(size_t)row * EP_LDS + (2 * nn) * 8 + kst];
            __half h1 = ep[(size_t)row * EP_LDS + (2 * nn + 1) * 8 + kst];
            *(__half2*)(plane + (size_t)(bm + row) * 512 + n0 + 2 * nn) =
                __halves2half2(h0, h1);
        }
    }
}

// ============================================================================
// K2 (fused): CTA covers 16 batch rows x ALL 8 states x 128 y-cols.
// A row r -> plane k=r&7, b=bm*16+(r>>3). Epilogue: smem stage -> coalesced
// o_outk float4 streaming writes; butterfly-shuffle pi-mix over gid -> o_out.
// ============================================================================
__global__ __launch_bounds__(256, 2)
void gemm_k2(const __half* __restrict__ h16, const __half* __restrict__ Wo,
             const float* __restrict__ pi,
             float* __restrict__ o_outk, float* __restrict__ o_out)
{
    extern __shared__ __align__(128) char smem[];
    uint32_t sbase;
    asm("{ .reg .u64 t; cvta.to.shared.u64 t, %1; cvt.u32.u64 %0, t; }"
        : "=r"(sbase) : "l"(smem));

    const int tid = threadIdx.x, wid = tid >> 5, lane = tid & 31;
    const int gid = lane >> 2, tg = lane & 3;
    const int warpM = wid & 3, warpN = wid >> 2;
    const int bm = blockIdx.y;           // 16-row batch slab
    const int bn = blockIdx.x * BN;      // y base

    float acc[2][8][4];
    #pragma unroll
    for (int im = 0; im < 2; ++im)
        #pragma unroll
        for (int in = 0; in < 8; ++in)
            #pragma unroll
            for (int q = 0; q < 4; ++q) acc[im][in][q] = 0.0f;

    {
        const int row_ld = wid * 16 + (lane >> 1);
        const size_t plane = (size_t)B_DIM * 512;
        const __half* gA = h16 + (size_t)(row_ld & 7) * plane
                               + ((size_t)bm * 16 + (row_ld >> 3)) * 512;
        const __half* gB = Wo + (size_t)(bn + row_ld) * 512;
        mainloop_ptr<512>(gA, gB, sbase, acc);
    }

    // ---------- fused epilogue ----------
    __syncthreads();
    float* stage = (float*)smem;         // [16][1024] floats = 64KB

    #pragma unroll
    for (int im = 0; im < 2; ++im) {
        const int brow = warpM * 4 + im * 2;
        const int b0 = bm * 16 + brow;
        const float pk0 = pi[(size_t)b0 * 8 + gid];
        const float pk1 = pi[(size_t)(b0 + 1) * 8 + gid];
        #pragma unroll
        for (int in = 0; in < 8; ++in) {
            const int y = warpN * 64 + in * 8 + tg * 2;   // local y
            float v0 = acc[im][in][0], v1 = acc[im][in][1];
            float v2 = acc[im][in][2], v3 = acc[im][in][3];

            stage[brow * 1024 + y * 8 + gid]             = v0;
            stage[brow * 1024 + (y + 1) * 8 + gid]       = v1;
            stage[(brow + 1) * 1024 + y * 8 + gid]       = v2;
            stage[(brow + 1) * 1024 + (y + 1) * 8 + gid] = v3;

            float m0 = v0 * pk0, m1 = v1 * pk0;
            float m2 = v2 * pk1, m3 = v3 * pk1;
            #pragma unroll
            for (int d = 4; d < 32; d <<= 1) {
                m0 += __shfl_xor_sync(0xFFFFFFFFu, m0, d);
                m1 += __shfl_xor_sync(0xFFFFFFFFu, m1, d);
                m2 += __shfl_xor_sync(0xFFFFFFFFu, m2, d);
                m3 += __shfl_xor_sync(0xFFFFFFFFu, m3, d);
            }
            if (gid == 0) {
                stcs_f1(o_out + (size_t)b0 * 256 + bn + y, m0);
                stcs_f1(o_out + (size_t)b0 * 256 + bn + y + 1, m1);
                stcs_f1(o_out + (size_t)(b0 + 1) * 256 + bn + y, m2);
                stcs_f1(o_out + (size_t)(b0 + 1) * 256 + bn + y + 1, m3);
            }
        }
    }
    __syncthreads();

    #pragma unroll
    for (int i = 0; i < 16; ++i) {
        const int idx = i * 256 + tid;
        const int brow = idx >> 8;
        const int chunk = idx & 255;
        float4 v = *(float4*)&stage[brow * 1024 + chunk * 4];
        stcs_f4(o_outk + ((size_t)(bm * 16 + brow) * 256 + bn) * 8 + chunk * 4, v);
    }
}

extern "C" void kernel_launch(void* const* d_in, const int* in_sizes, int n_in,
                              void* d_out, int out_size)
{
    const float* x     = (const float*)d_in[0];
    const float* h     = (const float*)d_in[1];
    const float* pi    = (const float*)d_in[2];
    const float* W_ih  = (const float*)d_in[3];
    const float* W_hh  = (const float*)d_in[4];
    const float* W_out = (const float*)d_in[5];
    float* out = (float*)d_out;

    __half *A16, *B16, *Wo16, *h16;
    cudaGetSymbolAddress((void**)&A16, g_A16);
    cudaGetSymbolAddress((void**)&B16, g_B16);
    cudaGetSymbolAddress((void**)&Wo16, g_Wo16);
    cudaGetSymbolAddress((void**)&h16, g_h16);

    // output layout: tuple (out, h_mix, out_k, h_k) concatenated, each row-major
    float* o_out  = out;                                   // (B, NY)
    float* o_mix  = o_out  + (size_t)B_DIM * NY;           // (B, NH)
    float* o_outk = o_mix  + (size_t)B_DIM * NH;           // (B, NY, K)
    float* o_hk   = o_outk + (size_t)B_DIM * NY * KSTATES; // (B, NH, K)

    cudaFuncSetAttribute(gemm_k1, cudaFuncAttributeMaxDynamicSharedMemorySize, SMEM_BYTES);
    cudaFuncSetAttribute(gemm_k2, cudaFuncAttributeMaxDynamicSharedMemorySize, SMEM_BYTES);

    // K0: fp16 operand packing (A16=[x|h], B16=interleaved Bv, Wo16)
    cvt_all<<<(NA_G + NB_G + NW_G + 255) / 256, 256>>>(
        x, h, W_ih, W_hh, W_out, A16, B16, Wo16);

    // K1: big GEMM -> o_hk (streaming) + o_mix + h16
    gemm_k1<<<dim3(4096 / BN, B_DIM / BM), 256, SMEM_BYTES>>>(
        A16, B16, pi, o_hk, o_mix, h16);

    // K2: fused out_k + out (interleave + pi-mix in epilogue)
    gemm_k2<<<dim3(NY / BN, B_DIM / 16), 256, SMEM_BYTES>>>(
        h16, Wo16, pi, o_outk, o_out);
}

// round 14
// speedup vs baseline: 1.3882x; 1.0457x over previous
#include <cuda_runtime.h>
#include <cuda_fp16.h>
#include <math.h>
#include <stdint.h>

// ---------------- problem constants ----------------
#define B_DIM 4096
#define NH 512
#define NY 256
#define KSTATES 8

// ---------------- GEMM tiling ----------------
#define BM 128
#define BN 128
#define BK 64              // halves per k-stage (128 bytes/row)
#define NSTAGE 3
#define STAGE_BYTES 32768  // A 16KB + B 16KB
#define SMEM_BYTES (NSTAGE * STAGE_BYTES)   // 96KB -> 2 CTAs/SM
#define EP_LDS 132         // K1 epilogue staging row stride (halves)

#define N_K1_TILES 1024    // 32 bn x 32 bm
#define N_K2_TILES 512     // 2 bn x 256 slabs
#define N_TILES (N_K1_TILES + N_K2_TILES)

// ---------------- device scratch (allocation-free) ----------------
__device__ __align__(16) __half g_A16[(size_t)B_DIM * 1024];             // [x|h] fp16
__device__ __align__(16) __half g_B16[(size_t)NH * KSTATES * 1024];      // Bv interleaved rows (n*8+k)
__device__ __align__(16) __half g_Wo16[(size_t)NY * NH];                 // W_out fp16
__device__ __align__(16) __half g_h16[(size_t)KSTATES * B_DIM * NH];     // tanh(h_k) fp16, k-major
__device__ int g_rb_ctr[32];   // per-row-block K1 completion counters
__device__ int g_queue;        // work queue head

// ============================================================================
// One-shot fp32 -> fp16 conversion / packing + counter reset (graph-safe)
// ============================================================================
#define NA_G (B_DIM * 1024 / 4)
#define NB_G (NH * KSTATES * 1024 / 4)
#define NW_G (NY * NH / 4)

__global__ __launch_bounds__(256)
void cvt_all(const float* __restrict__ x, const float* __restrict__ h,
             const float* __restrict__ W_ih, const float* __restrict__ W_hh,
             const float* __restrict__ W_out,
             __half* __restrict__ A16, __half* __restrict__ B16,
             __half* __restrict__ Wo16)
{
    int idx = blockIdx.x * blockDim.x + threadIdx.x;
    if (idx < 32) g_rb_ctr[idx] = 0;
    if (idx == 32) g_queue = 0;

    const float* src;
    __half* dst;
    if (idx < NA_G) {
        int d = idx * 4, b = d >> 10, c = d & 1023;
        src = (c < 512) ? (x + (size_t)b * 512 + c) : (h + (size_t)b * 512 + (c - 512));
        dst = A16 + d;
    } else if (idx < NA_G + NB_G) {
        int d = (idx - NA_G) * 4;
        int row = d >> 10, c = d & 1023;
        int n = row >> 3, k = row & 7;                  // interleaved row = n*8+k
        src = (c < 512) ? (W_ih + (size_t)((k * 512) + n) * 512 + c)
                        : (W_hh + (size_t)((k * 512) + n) * 512 + (c - 512));
        dst = B16 + d;
    } else if (idx < NA_G + NB_G + NW_G) {
        int d = (idx - NA_G - NB_G) * 4;
        src = W_out + d;
        dst = Wo16 + d;
    } else {
        return;
    }
    float4 f = *(const float4*)src;
    __half2 lo = __floats2half2_rn(f.x, f.y);
    __half2 hi = __floats2half2_rn(f.z, f.w);
    *(uint2*)dst = make_uint2(*(uint32_t*)&lo, *(uint32_t*)&hi);
}

// ---------------- mma / ldmatrix helpers ----------------
static __device__ __forceinline__ void ldsm4(uint32_t& r0, uint32_t& r1,
                                             uint32_t& r2, uint32_t& r3, uint32_t addr) {
    asm volatile("ldmatrix.sync.aligned.m8n8.x4.shared.b16 {%0,%1,%2,%3}, [%4];"
                 : "=r"(r0), "=r"(r1), "=r"(r2), "=r"(r3) : "r"(addr));
}
static __device__ __forceinline__ void mma16816(float (&c)[4], const uint32_t (&a)[4],
                                                uint32_t b0, uint32_t b1) {
    asm volatile(
        "mma.sync.aligned.m16n8k16.row.col.f32.f16.f16.f32 "
        "{%0,%1,%2,%3}, {%4,%5,%6,%7}, {%8,%9}, {%0,%1,%2,%3};\n"
        : "+f"(c[0]), "+f"(c[1]), "+f"(c[2]), "+f"(c[3])
        : "r"(a[0]), "r"(a[1]), "r"(a[2]), "r"(a[3]), "r"(b0), "r"(b1));
}
// streaming stores (evict-first; outputs are never re-read)
static __device__ __forceinline__ void stcs_f2(float* p, float2 v) {
    asm volatile("st.global.cs.v2.f32 [%0], {%1,%2};" :: "l"(p), "f"(v.x), "f"(v.y) : "memory");
}
static __device__ __forceinline__ void stcs_f4(float* p, float4 v) {
    asm volatile("st.global.cs.v4.f32 [%0], {%1,%2,%3,%4};"
                 :: "l"(p), "f"(v.x), "f"(v.y), "f"(v.z), "f"(v.w) : "memory");
}
static __device__ __forceinline__ void stcs_f1(float* p, float v) {
    asm volatile("st.global.cs.f32 [%0], %1;" :: "l"(p), "f"(v) : "memory");
}

// ============================================================================
// Mainloop core: acc[2][8][4] += A_tile(128,KD) * B_tile(128,KD)^T  (R9)
// ============================================================================
template<int KD>
static __device__ __forceinline__
void mainloop_ptr(const __half* __restrict__ gA, const __half* __restrict__ gB,
                  uint32_t sbase, float (&acc)[2][8][4])
{
    const int tid = threadIdx.x, wid = tid >> 5, lane = tid & 31;
    const int warpM = wid & 3, warpN = wid >> 2;

    const int row_ld = wid * 16 + (lane >> 1);
    const int cb = (lane & 1) * 4;

    auto issue = [&](int kt, int bi) {
        const uint32_t sA = sbase + bi * STAGE_BYTES;
        const __half* ga = gA + kt * BK;
        const __half* gb = gB + kt * BK;
        #pragma unroll
        for (int i = 0; i < 4; ++i) {
            int c = cb + i;
            uint32_t sw = (uint32_t)row_ld * 128 + (uint32_t)((c ^ (row_ld & 7)) * 16);
            asm volatile("cp.async.cg.shared.global [%0], [%1], 16;"
                         :: "r"(sA + sw), "l"(ga + c * 8));
            asm volatile("cp.async.cg.shared.global [%0], [%1], 16;"
                         :: "r"(sA + 16384 + sw), "l"(gb + c * 8));
        }
    };

    const int rwi  = lane & 7;
    const int hi8  = (lane >> 3) & 1;
    const int hi16 = lane >> 4;
    const int rowA0 = warpM * 32 + hi8 * 8 + rwi;
    const int rowB0 = warpN * 64 + hi8 * 8 + rwi;

    constexpr int NSTEPS = KD / BK;

    #pragma unroll
    for (int s = 0; s < NSTAGE - 1; ++s) {
        issue(s, s);
        asm volatile("cp.async.commit_group;" ::: "memory");
    }

    int bi = 0, bnx = NSTAGE - 1;
    for (int it = 0; it < NSTEPS; ++it) {
        asm volatile("cp.async.wait_group %0;" :: "n"(NSTAGE - 2) : "memory");
        __syncthreads();

        const int nx = it + NSTAGE - 1;
        if (nx < NSTEPS) issue(nx, bnx);
        asm volatile("cp.async.commit_group;" ::: "memory");

        const uint32_t sA = sbase + bi * STAGE_BYTES;
        const uint32_t sB = sA + 16384;
        if (++bi == NSTAGE) bi = 0;
        if (++bnx == NSTAGE) bnx = 0;

        #pragma unroll
        for (int kk = 0; kk < 4; ++kk) {
            const uint32_t chx = (uint32_t)(((2 * kk + hi16) ^ rwi) << 4);
            uint32_t a[2][4];
            #pragma unroll
            for (int im = 0; im < 2; ++im)
                ldsm4(a[im][0], a[im][1], a[im][2], a[im][3],
                      sA + (uint32_t)(rowA0 + im * 16) * 128 + chx);
            #pragma unroll
            for (int j = 0; j < 4; ++j) {
                uint32_t q0, q1, q2, q3;
                ldsm4(q0, q1, q2, q3, sB + (uint32_t)(rowB0 + j * 16) * 128 + chx);
                #pragma unroll
                for (int im = 0; im < 2; ++im) {
                    mma16816(acc[im][2 * j],     a[im], q0, q2);
                    mma16816(acc[im][2 * j + 1], a[im], q1, q3);
                }
            }
        }
    }
}

// ============================================================================
// K1 tile body (R9 gemm_k1 with bm/bn parameters) + completion arrival
// ============================================================================
static __device__ __forceinline__
void k1_tile(int bmIdx, int bnIdx,
             const __half* __restrict__ A, const __half* __restrict__ Bv,
             const float* __restrict__ pi,
             float* __restrict__ o_hk, float* __restrict__ o_mix,
             __half* __restrict__ h16, char* smem, uint32_t sbase)
{
    const int tid = threadIdx.x, wid = tid >> 5, lane = tid & 31;
    const int gid = lane >> 2, tg = lane & 3;
    const int warpM = wid & 3, warpN = wid >> 2;
    const int bm = bmIdx * BM, bn = bnIdx * BN;

    float acc[2][8][4];
    #pragma unroll
    for (int im = 0; im < 2; ++im)
        #pragma unroll
        for (int in = 0; in < 8; ++in)
            #pragma unroll
            for (int q = 0; q < 4; ++q) acc[im][in][q] = 0.0f;

    {
        const int row_ld = wid * 16 + (lane >> 1);
        const __half* gA = A + (size_t)(bm + row_ld) * 1024;
        const __half* gB = Bv + (size_t)(bn + row_ld) * 1024;
        mainloop_ptr<1024>(gA, gB, sbase, acc);
    }

    __syncthreads();
    __half* ep = (__half*)smem;          // 128 x EP_LDS staging
    const int n0 = bn >> 3;

    #pragma unroll
    for (int im = 0; im < 2; ++im) {
        const int rA = bm + warpM * 32 + im * 16 + gid;
        const float2 pA = *(const float2*)(pi + (size_t)rA * 8 + tg * 2);
        const float2 pB = *(const float2*)(pi + (size_t)(rA + 8) * 8 + tg * 2);
        #pragma unroll
        for (int in = 0; in < 8; ++in) {
            const int c0 = bn + warpN * 64 + in * 8 + tg * 2;
            float v0 = tanhf(acc[im][in][0]);
            float v1 = tanhf(acc[im][in][1]);
            float v2 = tanhf(acc[im][in][2]);
            float v3 = tanhf(acc[im][in][3]);

            stcs_f2(o_hk + (size_t)rA * 4096 + c0,       make_float2(v0, v1));
            stcs_f2(o_hk + (size_t)(rA + 8) * 4096 + c0, make_float2(v2, v3));

            float m0 = v0 * pA.x + v1 * pA.y;
            float m1 = v2 * pB.x + v3 * pB.y;
            m0 += __shfl_xor_sync(0xFFFFFFFFu, m0, 1);
            m0 += __shfl_xor_sync(0xFFFFFFFFu, m0, 2);
            m1 += __shfl_xor_sync(0xFFFFFFFFu, m1, 1);
            m1 += __shfl_xor_sync(0xFFFFFFFFu, m1, 2);
            if (tg == 0) {
                const int ng = n0 + warpN * 8 + in;
                stcs_f1(o_mix + (size_t)rA * 512 + ng, m0);
                stcs_f1(o_mix + (size_t)(rA + 8) * 512 + ng, m1);
            }

            const int rl = warpM * 32 + im * 16 + gid;
            const int cl = warpN * 64 + in * 8 + tg * 2;
            __half2 h01 = __floats2half2_rn(v0, v1);
            __half2 h23 = __floats2half2_rn(v2, v3);
            *(__half2*)(ep + (size_t)rl * EP_LDS + cl)       = h01;
            *(__half2*)(ep + (size_t)(rl + 8) * EP_LDS + cl) = h23;
        }
    }
    __syncthreads();

    // restage to h16 k-major: warp wid owns state k = wid
    {
        const int kst = wid;
        __half* plane = h16 + (size_t)kst * ((size_t)B_DIM * 512);
        const int rr = lane >> 3;
        const int nn = lane & 7;
        #pragma unroll
        for (int i = 0; i < 32; ++i) {
            const int row = i * 4 + rr;
            __half h0 = ep[(size_t)row * EP_LDS + (2 * nn) * 8 + kst];
            __half h1 = ep[(size_t)row * EP_LDS + (2 * nn + 1) * 8 + kst];
            *(__half2*)(plane + (size_t)(bm + row) * 512 + n0 + 2 * nn) =
                __halves2half2(h0, h1);
        }
    }

    // release: make h16 visible, then arrive on the row-block counter
    __threadfence();
    __syncthreads();
    if (tid == 0) atomicAdd(&g_rb_ctr[bmIdx], 1);
}

// ============================================================================
// K2 tile body (R9 gemm_k2 with slab/bn parameters) + dependency wait
// ============================================================================
static __device__ __forceinline__
void k2_tile(int slab, int bn,
             const __half* __restrict__ h16, const __half* __restrict__ Wo,
             const float* __restrict__ pi,
             float* __restrict__ o_outk, float* __restrict__ o_out,
             char* smem, uint32_t sbase)
{
    const int tid = threadIdx.x, wid = tid >> 5, lane = tid & 31;
    const int gid = lane >> 2, tg = lane & 3;
    const int warpM = wid & 3, warpN = wid >> 2;
    const int rb = slab >> 3;            // row block this slab depends on

    // acquire: wait for all 32 K1 tiles of this row block
    if (tid == 0) {
        while (atomicAdd(&g_rb_ctr[rb], 0) != 32) { }
        __threadfence();
    }
    __syncthreads();

    float acc[2][8][4];
    #pragma unroll
    for (int im = 0; im < 2; ++im)
        #pragma unroll
        for (int in = 0; in < 8; ++in)
            #pragma unroll
            for (int q = 0; q < 4; ++q) acc[im][in][q] = 0.0f;

    {
        const int row_ld = wid * 16 + (lane >> 1);
        const size_t plane = (size_t)B_DIM * 512;
        const __half* gA = h16 + (size_t)(row_ld & 7) * plane
                               + ((size_t)slab * 16 + (row_ld >> 3)) * 512;
        const __half* gB = Wo + (size_t)(bn + row_ld) * 512;
        mainloop_ptr<512>(gA, gB, sbase, acc);
    }

    __syncthreads();
    float* stage = (float*)smem;         // [16][1024] floats

    #pragma unroll
    for (int im = 0; im < 2; ++im) {
        const int brow = warpM * 4 + im * 2;
        const int b0 = slab * 16 + brow;
        const float pk0 = pi[(size_t)b0 * 8 + gid];
        const float pk1 = pi[(size_t)(b0 + 1) * 8 + gid];
        #pragma unroll
        for (int in = 0; in < 8; ++in) {
            const int y = warpN * 64 + in * 8 + tg * 2;
            float v0 = acc[im][in][0], v1 = acc[im][in][1];
            float v2 = acc[im][in][2], v3 = acc[im][in][3];

            stage[brow * 1024 + y * 8 + gid]             = v0;
            stage[brow * 1024 + (y + 1) * 8 + gid]       = v1;
            stage[(brow + 1) * 1024 + y * 8 + gid]       = v2;
            stage[(brow + 1) * 1024 + (y + 1) * 8 + gid] = v3;

            float m0 = v0 * pk0, m1 = v1 * pk0;
            float m2 = v2 * pk1, m3 = v3 * pk1;
            #pragma unroll
            for (int d = 4; d < 32; d <<= 1) {
                m0 += __shfl_xor_sync(0xFFFFFFFFu, m0, d);
                m1 += __shfl_xor_sync(0xFFFFFFFFu, m1, d);
                m2 += __shfl_xor_sync(0xFFFFFFFFu, m2, d);
                m3 += __shfl_xor_sync(0xFFFFFFFFu, m3, d);
            }
            if (gid == 0) {
                stcs_f1(o_out + (size_t)b0 * 256 + bn + y, m0);
                stcs_f1(o_out + (size_t)b0 * 256 + bn + y + 1, m1);
                stcs_f1(o_out + (size_t)(b0 + 1) * 256 + bn + y, m2);
                stcs_f1(o_out + (size_t)(b0 + 1) * 256 + bn + y + 1, m3);
            }
        }
    }
    __syncthreads();

    #pragma unroll
    for (int i = 0; i < 16; ++i) {
        const int idx = i * 256 + tid;
        const int brow = idx >> 8;
        const int chunk = idx & 255;
        float4 v = *(float4*)&stage[brow * 1024 + chunk * 4];
        stcs_f4(o_outk + ((size_t)(slab * 16 + brow) * 256 + bn) * 8 + chunk * 4, v);
    }
}

// ============================================================================
// Fused kernel: atomic work queue over 1024 K1 tiles + 512 K2 tiles.
// K2 tiles gated on per-row-block K1 completion counters.
// ============================================================================
__global__ __launch_bounds__(256, 2)
void gemm_fused(const __half* __restrict__ A, const __half* __restrict__ Bv,
                const __half* __restrict__ Wo, const float* __restrict__ pi,
                float* __restrict__ o_hk, float* __restrict__ o_mix,
                __half* __restrict__ h16,
                float* __restrict__ o_outk, float* __restrict__ o_out)
{
    extern __shared__ __align__(128) char smem[];
    uint32_t sbase;
    asm("{ .reg .u64 t; cvta.to.shared.u64 t, %1; cvt.u32.u64 %0, t; }"
        : "=r"(sbase) : "l"(smem));

    __shared__ int s_tile;
    if (threadIdx.x == 0) s_tile = atomicAdd(&g_queue, 1);
    __syncthreads();
    const int t = s_tile;

    if (t < N_K1_TILES) {
        k1_tile(t >> 5, t & 31, A, Bv, pi, o_hk, o_mix, h16, smem, sbase);
    } else {
        const int id = t - N_K1_TILES;
        k2_tile(id >> 1, (id & 1) * BN, h16, Wo, pi, o_outk, o_out, smem, sbase);
    }
}

extern "C" void kernel_launch(void* const* d_in, const int* in_sizes, int n_in,
                              void* d_out, int out_size)
{
    const float* x     = (const float*)d_in[0];
    const float* h     = (const float*)d_in[1];
    const float* pi    = (const float*)d_in[2];
    const float* W_ih  = (const float*)d_in[3];
    const float* W_hh  = (const float*)d_in[4];
    const float* W_out = (const float*)d_in[5];
    float* out = (float*)d_out;

    __half *A16, *B16, *Wo16, *h16;
    cudaGetSymbolAddress((void**)&A16, g_A16);
    cudaGetSymbolAddress((void**)&B16, g_B16);
    cudaGetSymbolAddress((void**)&Wo16, g_Wo16);
    cudaGetSymbolAddress((void**)&h16, g_h16);

    // output layout: tuple (out, h_mix, out_k, h_k) concatenated, each row-major
    float* o_out  = out;                                   // (B, NY)
    float* o_mix  = o_out  + (size_t)B_DIM * NY;           // (B, NH)
    float* o_outk = o_mix  + (size_t)B_DIM * NH;           // (B, NY, K)
    float* o_hk   = o_outk + (size_t)B_DIM * NY * KSTATES; // (B, NH, K)

    cudaFuncSetAttribute(gemm_fused, cudaFuncAttributeMaxDynamicSharedMemorySize, SMEM_BYTES);

    // K0: fp16 operand packing + counter/queue reset (replay-safe)
    cvt_all<<<(NA_G + NB_G + NW_G + 255) / 256, 256>>>(
        x, h, W_ih, W_hh, W_out, A16, B16, Wo16);

    // Fused K1+K2: work queue with dependency gating
    gemm_fused<<<N_TILES, 256, SMEM_BYTES>>>(
        A16, B16, Wo16, pi, o_hk, o_mix, h16, o_outk, o_out);
}